// round 10
// baseline (speedup 1.0000x reference)
#include <cuda_runtime.h>
#include <cstdint>

#define NROWS 8192
#define DDIM  256

// ---------------- device scratch (allocation-free) ----------------
// tf32-rounded copies, with each 8-column K-group permuted to fragment order
// {0,4,1,5,2,6,3,7} so MMA fragment pairs (k, k+4) are adjacent in memory.
__device__ float g_t[2][NROWS * DDIM];
__device__ float g_sq[2][NROWS];         // exact fp32 row norms

// ---------------- helpers ----------------
__device__ __forceinline__ uint32_t smem_u32(const void* p) {
    uint32_t a;
    asm("{ .reg .u64 t; cvta.to.shared.u64 t, %1; cvt.u32.u64 %0, t; }" : "=r"(a) : "l"(p));
    return a;
}
__device__ __forceinline__ uint2 lds64(uint32_t a) {
    uint2 v;
    asm volatile("ld.shared.v2.b32 {%0,%1}, [%2];" : "=r"(v.x), "=r"(v.y) : "r"(a));
    return v;
}
__device__ __forceinline__ void cp16(uint32_t dst, const void* src) {
    asm volatile("cp.async.cg.shared.global [%0], [%1], 16;" :: "r"(dst), "l"(src));
}
__device__ __forceinline__ void cp_commit() {
    asm volatile("cp.async.commit_group;" ::: "memory");
}
template <int N> __device__ __forceinline__ void cp_wait() {
    asm volatile("cp.async.wait_group %0;" :: "n"(N) : "memory");
}
__device__ __forceinline__ void mma_tf32(float* c, const uint32_t* a, const uint32_t* b) {
    asm volatile(
        "mma.sync.aligned.m16n8k8.row.col.f32.tf32.tf32.f32 "
        "{%0,%1,%2,%3}, {%4,%5,%6,%7}, {%8,%9}, {%0,%1,%2,%3};"
        : "+f"(c[0]), "+f"(c[1]), "+f"(c[2]), "+f"(c[3])
        : "r"(a[0]), "r"(a[1]), "r"(a[2]), "r"(a[3]), "r"(b[0]), "r"(b[1]));
}

// ---------------- prep: tf32-round + K-permute + exact row norms ----------------
__global__ void prep_kernel(const float* __restrict__ x1, const float* __restrict__ x2) {
    __shared__ float buf[8][256];
    int wib   = threadIdx.x >> 5;                              // warp in block
    int gw    = (blockIdx.x * blockDim.x + threadIdx.x) >> 5;  // global warp [0,16384)
    int lane  = threadIdx.x & 31;
    int which = gw >> 13;                 // 0 -> x1, 1 -> x2
    int row   = gw & (NROWS - 1);
    const float4* src = reinterpret_cast<const float4*>((which ? x2 : x1) + (size_t)row * DDIM);

    float s = 0.f;
#pragma unroll
    for (int i = 0; i < 2; i++) {
        int q = lane + 32 * i;            // 64 float4 per row
        float4 v = src[q];
        s += v.x * v.x + v.y * v.y + v.z * v.z + v.w * v.w;   // exact fp32 norm
        *reinterpret_cast<float4*>(&buf[wib][q * 4]) = v;
    }
    __syncwarp();
#pragma unroll
    for (int off = 16; off; off >>= 1) s += __shfl_xor_sync(0xffffffff, s, off);
    if (lane == 0) g_sq[which][row] = s;

    // permuted + tf32-rounded writeback: position p in 8-group holds orig col
    // c = (p&1) ? p/2 + 4 : p/2
    float* dst = &g_t[which][(size_t)row * DDIM];
#pragma unroll
    for (int i = 0; i < 8; i++) {
        int j = i * 32 + lane;
        int p = j & 7;
        int c = (p & 1) ? (p >> 1) + 4 : (p >> 1);
        float v = buf[wib][(j & ~7) + c];
        uint32_t t;
        asm("cvt.rna.tf32.f32 %0, %1;" : "=r"(t) : "f"(v));
        dst[j] = __uint_as_float(t);
    }
}

// ---------------- main GEMM + epilogue ----------------
#define BM 128
#define BN 128
#define BK 32
#define NK (DDIM / BK)            // 8 K-iterations
#define STAGES 3
#define ROWB 128                  // 32 floats per smem row, no padding (XOR swizzle)
#define MAT_BYTES (BM * ROWB)     // 16384
#define STAGE_BYTES (2 * MAT_BYTES)
#define SMEM_TOTAL (STAGES * STAGE_BYTES)   // 98304 -> 2 CTAs/SM

// 4 warps (128 threads); each warp owns a 64x64 output tile.
__global__ void __launch_bounds__(128, 2)
cdist_kernel(float* __restrict__ out) {
    extern __shared__ char smem_raw[];
    const uint32_t sbase = smem_u32(smem_raw);

    const int tid = threadIdx.x;
    const int wid = tid >> 5;
    const int lid = tid & 31;
    const int m0 = blockIdx.y * BM;
    const int n0 = blockIdx.x * BN;
    const int g   = lid >> 2;         // 0..7
    const int tig = lid & 3;          // 0..3
    const int wm = (wid & 1) * 64;    // warp m-offset (2 warps in M)
    const int wn = (wid >> 1) * 64;   // warp n-offset (2 warps in N)

    const float* Ag = g_t[0] + (size_t)m0 * DDIM;
    const float* Bg = g_t[1] + (size_t)n0 * DDIM;

    // per-thread copy coords: 1024 16B chunks per matrix per stage, 8 per thread
    const int cm = tid >> 3;          // base row (0..15)
    const int kq = tid & 7;           // 16B sub-chunk within 32-float K slice

    auto load_stage = [&](int kc, int s) {
        const uint32_t sA = sbase + (uint32_t)s * STAGE_BYTES;
        const uint32_t sB = sA + MAT_BYTES;
        const size_t gk = (size_t)kc * BK + (size_t)kq * 4;
#pragma unroll
        for (int i = 0; i < 8; i++) {
            int m = cm + i * 16;
            size_t go = (size_t)m * DDIM + gk;
            uint32_t so = (uint32_t)m * ROWB
                        + (((uint32_t)kq * 16u) ^ (((uint32_t)m & 3u) << 5));
            cp16(sA + so, Ag + go);
            cp16(sB + so, Bg + go);
        }
        cp_commit();
    };

    // prologue: STAGES-1 stages in flight
    load_stage(0, 0);
    load_stage(1, 1);

    float c[4][8][4];
#pragma unroll
    for (int mt = 0; mt < 4; mt++)
#pragma unroll
        for (int nt = 0; nt < 8; nt++)
#pragma unroll
            for (int i = 0; i < 4; i++) c[mt][nt][i] = 0.f;

    for (int kc = 0; kc < NK; kc++) {
        cp_wait<STAGES - 2>();     // stage kc landed
        __syncthreads();           // all warps' fills visible; frees oldest buf

        if (kc + STAGES - 1 < NK) load_stage(kc + STAGES - 1, (kc + STAGES - 1) % STAGES);
        else cp_commit();          // empty group keeps wait_group arithmetic uniform

        const uint32_t sA = sbase + (uint32_t)(kc % STAGES) * STAGE_BYTES;
        const uint32_t sB = sA + MAT_BYTES;

        // per-fragment swizzled base addresses; per-ks address = base ^ (ks<<5)
        uint32_t abase[4], bbase[8];
#pragma unroll
        for (int mt = 0; mt < 4; mt++) {
            uint32_t r = (uint32_t)(wm + mt * 16 + g);
            abase[mt] = sA + r * ROWB + ((r & 3u) << 5) + (uint32_t)tig * 8u;
        }
#pragma unroll
        for (int nt = 0; nt < 8; nt++) {
            uint32_t r = (uint32_t)(wn + nt * 8 + g);
            bbase[nt] = sB + r * ROWB + ((r & 3u) << 5) + (uint32_t)tig * 8u;
        }

#pragma unroll
        for (int ks = 0; ks < 4; ks++) {
            const uint32_t kx = (uint32_t)ks << 5;
            uint32_t a[4][4], b[8][2];
#pragma unroll
            for (int mt = 0; mt < 4; mt++) {
                uint32_t addr = abase[mt] ^ kx;
                uint2 lo = lds64(addr);
                uint2 hi = lds64(addr + 8u * ROWB);    // row+8: same swizzle class
                a[mt][0] = lo.x;  a[mt][2] = lo.y;     // (g,   tig), (g,   tig+4)
                a[mt][1] = hi.x;  a[mt][3] = hi.y;     // (g+8, tig), (g+8, tig+4)
            }
#pragma unroll
            for (int nt = 0; nt < 8; nt++) {
                uint2 bb = lds64(bbase[nt] ^ kx);
                b[nt][0] = bb.x;  b[nt][1] = bb.y;     // (n=g, k=tig), (n=g, k=tig+4)
            }
#pragma unroll
            for (int mt = 0; mt < 4; mt++)
#pragma unroll
                for (int nt = 0; nt < 8; nt++)
                    mma_tf32(c[mt][nt], a[mt], b[nt]);
        }
    }

    // ---- epilogue: d = sqrt(max(sq1 + sq2 - 2*cross, 0)) ----
    const float* sq1 = g_sq[0] + m0;
    const float* sq2 = g_sq[1] + n0;
#pragma unroll
    for (int mt = 0; mt < 4; mt++) {
        int r0 = wm + mt * 16 + g;
        float s1a = sq1[r0];
        float s1b = sq1[r0 + 8];
        float* o0 = out + (size_t)(m0 + r0) * NROWS + n0;
        float* o1 = o0 + (size_t)8 * NROWS;
#pragma unroll
        for (int nt = 0; nt < 8; nt++) {
            int cc = wn + nt * 8 + 2 * tig;
            float s2a = sq2[cc];
            float s2b = sq2[cc + 1];
            float2 v0, v1;
            v0.x = sqrtf(fmaxf(fmaf(-2.f, c[mt][nt][0], s1a + s2a), 0.f));
            v0.y = sqrtf(fmaxf(fmaf(-2.f, c[mt][nt][1], s1a + s2b), 0.f));
            v1.x = sqrtf(fmaxf(fmaf(-2.f, c[mt][nt][2], s1b + s2a), 0.f));
            v1.y = sqrtf(fmaxf(fmaf(-2.f, c[mt][nt][3], s1b + s2b), 0.f));
            *reinterpret_cast<float2*>(o0 + cc) = v0;
            *reinterpret_cast<float2*>(o1 + cc) = v1;
        }
    }
}

// ---------------- launch ----------------
extern "C" void kernel_launch(void* const* d_in, const int* in_sizes, int n_in,
                              void* d_out, int out_size) {
    (void)in_sizes; (void)n_in; (void)out_size;
    const float* x1 = (const float*)d_in[0];
    const float* x2 = (const float*)d_in[1];
    float* out = (float*)d_out;

    prep_kernel<<<2048, 256>>>(x1, x2);

    static bool attr_set = false;
    if (!attr_set) {
        cudaFuncSetAttribute(cdist_kernel,
                             cudaFuncAttributeMaxDynamicSharedMemorySize, SMEM_TOTAL);
        attr_set = true;
    }
    dim3 grid(NROWS / BN, NROWS / BM);   // (64, 64)
    cdist_kernel<<<grid, 128, SMEM_TOTAL>>>(out);
}

// round 11
// speedup vs baseline: 1.1411x; 1.1411x over previous
#include <cuda_runtime.h>
#include <cstdint>

#define NROWS 8192
#define DDIM  256

// ---------------- device scratch (allocation-free) ----------------
// tf32-rounded copies, with each 8-column K-group permuted to fragment order
// {0,4,1,5,2,6,3,7} so MMA fragment pairs (k, k+4) are adjacent in memory.
__device__ float g_t[2][NROWS * DDIM];
__device__ float g_sq[2][NROWS];         // exact fp32 row norms

// ---------------- helpers ----------------
__device__ __forceinline__ uint32_t smem_u32(const void* p) {
    uint32_t a;
    asm("{ .reg .u64 t; cvta.to.shared.u64 t, %1; cvt.u32.u64 %0, t; }" : "=r"(a) : "l"(p));
    return a;
}
__device__ __forceinline__ uint2 lds64(uint32_t a) {
    uint2 v;
    asm volatile("ld.shared.v2.b32 {%0,%1}, [%2];" : "=r"(v.x), "=r"(v.y) : "r"(a));
    return v;
}
__device__ __forceinline__ uint2 lds64_off(uint32_t a, int imm) {
    uint2 v;
    asm volatile("ld.shared.v2.b32 {%0,%1}, [%2+1024];" : "=r"(v.x), "=r"(v.y) : "r"(a));
    (void)imm;
    return v;
}
__device__ __forceinline__ void cp16(uint32_t dst, const void* src) {
    asm volatile("cp.async.cg.shared.global [%0], [%1], 16;" :: "r"(dst), "l"(src));
}
__device__ __forceinline__ void cp_commit() {
    asm volatile("cp.async.commit_group;" ::: "memory");
}
template <int N> __device__ __forceinline__ void cp_wait() {
    asm volatile("cp.async.wait_group %0;" :: "n"(N) : "memory");
}
__device__ __forceinline__ void mma_tf32(float* c, const uint32_t* a, const uint32_t* b) {
    asm volatile(
        "mma.sync.aligned.m16n8k8.row.col.f32.tf32.tf32.f32 "
        "{%0,%1,%2,%3}, {%4,%5,%6,%7}, {%8,%9}, {%0,%1,%2,%3};"
        : "+f"(c[0]), "+f"(c[1]), "+f"(c[2]), "+f"(c[3])
        : "r"(a[0]), "r"(a[1]), "r"(a[2]), "r"(a[3]), "r"(b[0]), "r"(b[1]));
}

// ---------------- prep: tf32-round + K-permute + exact row norms ----------------
__global__ void prep_kernel(const float* __restrict__ x1, const float* __restrict__ x2) {
    __shared__ float buf[8][256];
    int wib   = threadIdx.x >> 5;                              // warp in block
    int gw    = (blockIdx.x * blockDim.x + threadIdx.x) >> 5;  // global warp [0,16384)
    int lane  = threadIdx.x & 31;
    int which = gw >> 13;                 // 0 -> x1, 1 -> x2
    int row   = gw & (NROWS - 1);
    const float4* src = reinterpret_cast<const float4*>((which ? x2 : x1) + (size_t)row * DDIM);

    float s = 0.f;
#pragma unroll
    for (int i = 0; i < 2; i++) {
        int q = lane + 32 * i;            // 64 float4 per row
        float4 v = src[q];
        s += v.x * v.x + v.y * v.y + v.z * v.z + v.w * v.w;   // exact fp32 norm
        *reinterpret_cast<float4*>(&buf[wib][q * 4]) = v;
    }
    __syncwarp();
#pragma unroll
    for (int off = 16; off; off >>= 1) s += __shfl_xor_sync(0xffffffff, s, off);
    if (lane == 0) g_sq[which][row] = s;

    // permuted + tf32-rounded writeback: position p in 8-group holds orig col
    // c = (p&1) ? p/2 + 4 : p/2
    float* dst = &g_t[which][(size_t)row * DDIM];
#pragma unroll
    for (int i = 0; i < 8; i++) {
        int j = i * 32 + lane;
        int p = j & 7;
        int c = (p & 1) ? (p >> 1) + 4 : (p >> 1);
        float v = buf[wib][(j & ~7) + c];
        uint32_t t;
        asm("cvt.rna.tf32.f32 %0, %1;" : "=r"(t) : "f"(v));
        dst[j] = __uint_as_float(t);
    }
}

// ---------------- main GEMM + epilogue ----------------
#define BM 128
#define BN 128
#define BK 32
#define NK (DDIM / BK)            // 8 K-iterations
#define STAGES 3
#define ROWB 128                  // 32 floats per smem row, no padding (XOR swizzle)
#define MAT_BYTES (BM * ROWB)     // 16384
#define STAGE_BYTES (2 * MAT_BYTES)
#define SMEM_TOTAL (STAGES * STAGE_BYTES)   // 98304 -> 2 CTAs/SM

__global__ void __launch_bounds__(256, 2)
cdist_kernel(float* __restrict__ out) {
    extern __shared__ char smem_raw[];
    const uint32_t sbase = smem_u32(smem_raw);

    const int tid = threadIdx.x;
    const int wid = tid >> 5;
    const int lid = tid & 31;
    const int m0 = blockIdx.y * BM;
    const int n0 = blockIdx.x * BN;
    const int g   = lid >> 2;         // 0..7
    const int tig = lid & 3;          // 0..3
    const int wm = (wid & 1) * 64;    // warp m-offset (2 warps in M)
    const int wn = (wid >> 1) * 32;   // warp n-offset (4 warps in N)

    // ---- loop-invariant cp.async addressing ----
    const int cm = tid >> 3;          // base row (0..31), rows step +32 per i
    const int kq = tid & 7;           // 16B sub-chunk within 32-float K slice
    // per-thread gmem base pointers (advance by immediates under full unroll)
    const char* gA = (const char*)g_t[0]
                   + ((size_t)(m0 + cm) * DDIM + (size_t)kq * 4) * 4;
    const char* gB = (const char*)g_t[1]
                   + ((size_t)(n0 + cm) * DDIM + (size_t)kq * 4) * 4;
    // per-thread smem base offsets (swizzle term constant: (cm+32i)&3 == cm&3)
    const uint32_t sdA = sbase + (uint32_t)cm * ROWB
                       + (((uint32_t)kq * 16u) ^ (((uint32_t)cm & 3u) << 5));
    const uint32_t sdB = sdA + MAT_BYTES;

    auto load_stage = [&](int kc, int s) {   // kc, s compile-time under unroll
#pragma unroll
        for (int i = 0; i < 4; i++) {
            cp16(sdA + s * STAGE_BYTES + i * (32 * ROWB), gA + kc * 128 + i * (32 * DDIM * 4));
            cp16(sdB + s * STAGE_BYTES + i * (32 * ROWB), gB + kc * 128 + i * (32 * DDIM * 4));
        }
        cp_commit();
    };

    // ---- loop-invariant fragment bases (stage 0) ----
    uint32_t abase[4], bbase[4];
#pragma unroll
    for (int mt = 0; mt < 4; mt++) {
        uint32_t r = (uint32_t)(wm + mt * 16 + g);
        abase[mt] = sbase + r * ROWB + ((r & 3u) << 5) + (uint32_t)tig * 8u;
    }
#pragma unroll
    for (int nt = 0; nt < 4; nt++) {
        uint32_t r = (uint32_t)(wn + nt * 8 + g);
        bbase[nt] = sbase + MAT_BYTES + r * ROWB + ((r & 3u) << 5) + (uint32_t)tig * 8u;
    }

    // prologue: STAGES-1 stages in flight
    load_stage(0, 0);
    load_stage(1, 1);

    float c[4][4][4];
#pragma unroll
    for (int mt = 0; mt < 4; mt++)
#pragma unroll
        for (int nt = 0; nt < 4; nt++)
#pragma unroll
            for (int i = 0; i < 4; i++) c[mt][nt][i] = 0.f;

#pragma unroll
    for (int kc = 0; kc < NK; kc++) {
        cp_wait<STAGES - 2>();     // stage kc landed
        __syncthreads();           // all warps done reading oldest buf

        if (kc + STAGES - 1 < NK) load_stage(kc + STAGES - 1, (kc + STAGES - 1) % STAGES);
        else cp_commit();          // empty group keeps wait_group arithmetic uniform

        const uint32_t soff = (uint32_t)((kc % STAGES) * STAGE_BYTES);
        uint32_t ab[4], bb[4];
#pragma unroll
        for (int mt = 0; mt < 4; mt++) ab[mt] = abase[mt] + soff;
#pragma unroll
        for (int nt = 0; nt < 4; nt++) bb[nt] = bbase[nt] + soff;

#pragma unroll
        for (int ks = 0; ks < 4; ks++) {
            const uint32_t kx = (uint32_t)ks << 5;   // pure bit toggle (bits 5-6)
            uint32_t a[4][4], b[4][2];
#pragma unroll
            for (int mt = 0; mt < 4; mt++) {
                uint32_t ad = ab[mt] ^ kx;
                uint2 lo = lds64(ad);
                uint2 hi = lds64_off(ad, 1024);        // row+8: same swizzle class
                a[mt][0] = lo.x;  a[mt][2] = lo.y;     // (g,   tig), (g,   tig+4)
                a[mt][1] = hi.x;  a[mt][3] = hi.y;     // (g+8, tig), (g+8, tig+4)
            }
#pragma unroll
            for (int nt = 0; nt < 4; nt++) {
                uint2 v = lds64(bb[nt] ^ kx);
                b[nt][0] = v.x;  b[nt][1] = v.y;       // (n=g, k=tig), (n=g, k=tig+4)
            }
#pragma unroll
            for (int mt = 0; mt < 4; mt++)
#pragma unroll
                for (int nt = 0; nt < 4; nt++)
                    mma_tf32(c[mt][nt], a[mt], b[nt]);
        }
    }

    // ---- epilogue: d = sqrt(max(sq1 + sq2 - 2*cross, 0)) ----
    const float* sq1 = g_sq[0] + m0;
    const float* sq2 = g_sq[1] + n0;
#pragma unroll
    for (int mt = 0; mt < 4; mt++) {
        int r0 = wm + mt * 16 + g;
        float s1a = sq1[r0];
        float s1b = sq1[r0 + 8];
        float* o0 = out + (size_t)(m0 + r0) * NROWS + n0;
        float* o1 = o0 + (size_t)8 * NROWS;
#pragma unroll
        for (int nt = 0; nt < 4; nt++) {
            int cc = wn + nt * 8 + 2 * tig;
            float s2a = sq2[cc];
            float s2b = sq2[cc + 1];
            float2 v0, v1;
            v0.x = sqrtf(fmaxf(fmaf(-2.f, c[mt][nt][0], s1a + s2a), 0.f));
            v0.y = sqrtf(fmaxf(fmaf(-2.f, c[mt][nt][1], s1a + s2b), 0.f));
            v1.x = sqrtf(fmaxf(fmaf(-2.f, c[mt][nt][2], s1b + s2a), 0.f));
            v1.y = sqrtf(fmaxf(fmaf(-2.f, c[mt][nt][3], s1b + s2b), 0.f));
            *reinterpret_cast<float2*>(o0 + cc) = v0;
            *reinterpret_cast<float2*>(o1 + cc) = v1;
        }
    }
}

// ---------------- launch ----------------
extern "C" void kernel_launch(void* const* d_in, const int* in_sizes, int n_in,
                              void* d_out, int out_size) {
    (void)in_sizes; (void)n_in; (void)out_size;
    const float* x1 = (const float*)d_in[0];
    const float* x2 = (const float*)d_in[1];
    float* out = (float*)d_out;

    prep_kernel<<<2048, 256>>>(x1, x2);

    static bool attr_set = false;
    if (!attr_set) {
        cudaFuncSetAttribute(cdist_kernel,
                             cudaFuncAttributeMaxDynamicSharedMemorySize, SMEM_TOTAL);
        attr_set = true;
    }
    dim3 grid(NROWS / BN, NROWS / BM);   // (64, 64)
    cdist_kernel<<<grid, 256, SMEM_TOTAL>>>(out);
}

// round 12
// speedup vs baseline: 1.1420x; 1.0007x over previous
#include <cuda_runtime.h>
#include <cstdint>

#define NROWS 8192
#define DDIM  256

// ---------------- device scratch (allocation-free) ----------------
// tf32-rounded copies; within each 16-column K-group, 16B granule q holds
// orig cols {q, q+4, q+8, q+12} — i.e. the MMA fragments (k, k+4) for two
// consecutive k-steps, for thread tig=q. One LDS.128 = 2 k-steps of frags.
__device__ float g_t[2][NROWS * DDIM];
__device__ float g_sq[2][NROWS];         // exact fp32 row norms

// ---------------- helpers ----------------
__device__ __forceinline__ uint32_t smem_u32(const void* p) {
    uint32_t a;
    asm("{ .reg .u64 t; cvta.to.shared.u64 t, %1; cvt.u32.u64 %0, t; }" : "=r"(a) : "l"(p));
    return a;
}
__device__ __forceinline__ uint4 lds128(uint32_t a) {
    uint4 v;
    asm volatile("ld.shared.v4.b32 {%0,%1,%2,%3}, [%4];"
                 : "=r"(v.x), "=r"(v.y), "=r"(v.z), "=r"(v.w) : "r"(a));
    return v;
}
__device__ __forceinline__ uint4 lds128_p1024(uint32_t a) {   // same addr + 1024 imm
    uint4 v;
    asm volatile("ld.shared.v4.b32 {%0,%1,%2,%3}, [%4+1024];"
                 : "=r"(v.x), "=r"(v.y), "=r"(v.z), "=r"(v.w) : "r"(a));
    return v;
}
__device__ __forceinline__ void cp16(uint32_t dst, const void* src) {
    asm volatile("cp.async.cg.shared.global [%0], [%1], 16;" :: "r"(dst), "l"(src));
}
__device__ __forceinline__ void cp_commit() {
    asm volatile("cp.async.commit_group;" ::: "memory");
}
template <int N> __device__ __forceinline__ void cp_wait() {
    asm volatile("cp.async.wait_group %0;" :: "n"(N) : "memory");
}
__device__ __forceinline__ void mma_tf32_r(float* c, uint32_t a0, uint32_t a1,
                                           uint32_t a2, uint32_t a3,
                                           uint32_t b0, uint32_t b1) {
    asm volatile(
        "mma.sync.aligned.m16n8k8.row.col.f32.tf32.tf32.f32 "
        "{%0,%1,%2,%3}, {%4,%5,%6,%7}, {%8,%9}, {%0,%1,%2,%3};"
        : "+f"(c[0]), "+f"(c[1]), "+f"(c[2]), "+f"(c[3])
        : "r"(a0), "r"(a1), "r"(a2), "r"(a3), "r"(b0), "r"(b1));
}

// ---------------- prep: tf32-round + 16-wide K-permute + exact row norms ----------------
__global__ void prep_kernel(const float* __restrict__ x1, const float* __restrict__ x2) {
    __shared__ float buf[8][256];
    int wib   = threadIdx.x >> 5;
    int gw    = (blockIdx.x * blockDim.x + threadIdx.x) >> 5;  // global warp [0,16384)
    int lane  = threadIdx.x & 31;
    int which = gw >> 13;                 // 0 -> x1, 1 -> x2
    int row   = gw & (NROWS - 1);
    const float4* src = reinterpret_cast<const float4*>((which ? x2 : x1) + (size_t)row * DDIM);

    float s = 0.f;
#pragma unroll
    for (int i = 0; i < 2; i++) {
        int q = lane + 32 * i;            // 64 float4 per row
        float4 v = src[q];
        s += v.x * v.x + v.y * v.y + v.z * v.z + v.w * v.w;   // exact fp32 norm
        *reinterpret_cast<float4*>(&buf[wib][q * 4]) = v;
    }
    __syncwarp();
#pragma unroll
    for (int off = 16; off; off >>= 1) s += __shfl_xor_sync(0xffffffff, s, off);
    if (lane == 0) g_sq[which][row] = s;

    // permuted + tf32-rounded writeback:
    // dst[grp*16 + 4q + j] = src[grp*16 + q + 4j]   (q, j in 0..3)
    float* dst = &g_t[which][(size_t)row * DDIM];
#pragma unroll
    for (int i = 0; i < 8; i++) {
        int j   = i * 32 + lane;          // dst index
        int grp = j & ~15;
        int p   = j & 15;
        float v = buf[wib][grp + (p >> 2) + 4 * (p & 3)];
        uint32_t t;
        asm("cvt.rna.tf32.f32 %0, %1;" : "=r"(t) : "f"(v));
        dst[j] = __uint_as_float(t);
    }
}

// ---------------- main GEMM + epilogue ----------------
#define BM 128
#define BN 128
#define BK 32
#define NK (DDIM / BK)            // 8 K-iterations
#define STAGES 3
#define ROWB 128                  // 32 floats per smem row (granule-XOR swizzle)
#define MAT_BYTES (BM * ROWB)     // 16384
#define STAGE_BYTES (2 * MAT_BYTES)
#define SMEM_TOTAL (STAGES * STAGE_BYTES)   // 98304 -> 2 CTAs/SM

__global__ void __launch_bounds__(256, 2)
cdist_kernel(float* __restrict__ out) {
    extern __shared__ char smem_raw[];
    const uint32_t sbase = smem_u32(smem_raw);

    const int tid = threadIdx.x;
    const int wid = tid >> 5;
    const int lid = tid & 31;
    const int m0 = blockIdx.y * BM;
    const int n0 = blockIdx.x * BN;
    const int g   = lid >> 2;         // 0..7
    const int tig = lid & 3;          // 0..3
    const int wm = (wid & 1) * 64;    // warp m-offset (2 warps in M)
    const int wn = (wid >> 1) * 32;   // warp n-offset (4 warps in N)

    // ---- loop-invariant cp.async addressing ----
    const int cm = tid >> 3;          // base row (0..31), rows step +32 per i
    const int kq = tid & 7;           // 16B granule within 32-float K slice
    const char* gA = (const char*)g_t[0]
                   + ((size_t)(m0 + cm) * DDIM + (size_t)kq * 4) * 4;
    const char* gB = (const char*)g_t[1]
                   + ((size_t)(n0 + cm) * DDIM + (size_t)kq * 4) * 4;
    // smem store: physical granule = kq ^ ((row&1)<<2); (cm+32i)&1 == cm&1
    const uint32_t sdA = sbase + (uint32_t)cm * ROWB
                       + (uint32_t)(kq ^ ((cm & 1) << 2)) * 16u;
    const uint32_t sdB = sdA + MAT_BYTES;

    auto load_stage = [&](int kc, int s) {   // kc, s compile-time under unroll
#pragma unroll
        for (int i = 0; i < 4; i++) {
            cp16(sdA + s * STAGE_BYTES + i * (32 * ROWB), gA + kc * 128 + i * (32 * DDIM * 4));
            cp16(sdB + s * STAGE_BYTES + i * (32 * ROWB), gB + kc * 128 + i * (32 * DDIM * 4));
        }
        cp_commit();
    };

    // ---- loop-invariant fragment bases (stage 0, kp=0) ----
    // addr(kp) = base ^ (kp<<6)  (bit 6 carries (g&1) from the granule swizzle)
    uint32_t abase[4], bbase[4];
#pragma unroll
    for (int mt = 0; mt < 4; mt++) {
        uint32_t r = (uint32_t)(wm + mt * 16 + g);
        abase[mt] = sbase + r * ROWB + (uint32_t)tig * 16u + (((uint32_t)g & 1u) << 6);
    }
#pragma unroll
    for (int nt = 0; nt < 4; nt++) {
        uint32_t r = (uint32_t)(wn + nt * 8 + g);
        bbase[nt] = sbase + MAT_BYTES + r * ROWB + (uint32_t)tig * 16u + (((uint32_t)g & 1u) << 6);
    }

    // prologue: STAGES-1 stages in flight
    load_stage(0, 0);
    load_stage(1, 1);

    float c[4][4][4];
#pragma unroll
    for (int mt = 0; mt < 4; mt++)
#pragma unroll
        for (int nt = 0; nt < 4; nt++)
#pragma unroll
            for (int i = 0; i < 4; i++) c[mt][nt][i] = 0.f;

#pragma unroll
    for (int kc = 0; kc < NK; kc++) {
        cp_wait<STAGES - 2>();     // stage kc landed
        __syncthreads();           // all warps done reading oldest buf

        if (kc + STAGES - 1 < NK) load_stage(kc + STAGES - 1, (kc + STAGES - 1) % STAGES);
        else cp_commit();          // empty group keeps wait_group arithmetic uniform

        const uint32_t soff = (uint32_t)((kc % STAGES) * STAGE_BYTES);

#pragma unroll
        for (int kp = 0; kp < 2; kp++) {      // 16-col half of the 32-col chunk
            const uint32_t kx = (uint32_t)kp << 6;

            // B fragments for both k-steps of this half: one LDS.128 per nt
            uint4 bv[4];
#pragma unroll
            for (int nt = 0; nt < 4; nt++)
                bv[nt] = lds128((bbase[nt] + soff) ^ kx);

            // software-pipelined A loads over mt-MMA blocks
            uint4 alo = lds128((abase[0] + soff) ^ kx);
            uint4 ahi = lds128_p1024((abase[0] + soff) ^ kx);
#pragma unroll
            for (int mt = 0; mt < 4; mt++) {
                uint4 nlo, nhi;
                if (mt < 3) {
                    uint32_t ad = (abase[mt + 1] + soff) ^ kx;
                    nlo = lds128(ad);
                    nhi = lds128_p1024(ad);
                }
                // k-step even: frags .x (k=tig), .y (k=tig+4)
#pragma unroll
                for (int nt = 0; nt < 4; nt++)
                    mma_tf32_r(c[mt][nt], alo.x, ahi.x, alo.y, ahi.y,
                               bv[nt].x, bv[nt].y);
                // k-step odd: frags .z (k=tig+8), .w (k=tig+12)
#pragma unroll
                for (int nt = 0; nt < 4; nt++)
                    mma_tf32_r(c[mt][nt], alo.z, ahi.z, alo.w, ahi.w,
                               bv[nt].z, bv[nt].w);
                alo = nlo; ahi = nhi;
            }
        }
    }

    // ---- epilogue: d = sqrt(max(sq1 + sq2 - 2*cross, 0)) ----
    const float* sq1 = g_sq[0] + m0;
    const float* sq2 = g_sq[1] + n0;
#pragma unroll
    for (int mt = 0; mt < 4; mt++) {
        int r0 = wm + mt * 16 + g;
        float s1a = sq1[r0];
        float s1b = sq1[r0 + 8];
        float* o0 = out + (size_t)(m0 + r0) * NROWS + n0;
        float* o1 = o0 + (size_t)8 * NROWS;
#pragma unroll
        for (int nt = 0; nt < 4; nt++) {
            int cc = wn + nt * 8 + 2 * tig;
            float s2a = sq2[cc];
            float s2b = sq2[cc + 1];
            float2 v0, v1;
            v0.x = sqrtf(fmaxf(fmaf(-2.f, c[mt][nt][0], s1a + s2a), 0.f));
            v0.y = sqrtf(fmaxf(fmaf(-2.f, c[mt][nt][1], s1a + s2b), 0.f));
            v1.x = sqrtf(fmaxf(fmaf(-2.f, c[mt][nt][2], s1b + s2a), 0.f));
            v1.y = sqrtf(fmaxf(fmaf(-2.f, c[mt][nt][3], s1b + s2b), 0.f));
            *reinterpret_cast<float2*>(o0 + cc) = v0;
            *reinterpret_cast<float2*>(o1 + cc) = v1;
        }
    }
}

// ---------------- launch ----------------
extern "C" void kernel_launch(void* const* d_in, const int* in_sizes, int n_in,
                              void* d_out, int out_size) {
    (void)in_sizes; (void)n_in; (void)out_size;
    const float* x1 = (const float*)d_in[0];
    const float* x2 = (const float*)d_in[1];
    float* out = (float*)d_out;

    prep_kernel<<<2048, 256>>>(x1, x2);

    static bool attr_set = false;
    if (!attr_set) {
        cudaFuncSetAttribute(cdist_kernel,
                             cudaFuncAttributeMaxDynamicSharedMemorySize, SMEM_TOTAL);
        attr_set = true;
    }
    dim3 grid(NROWS / BN, NROWS / BM);   // (64, 64)
    cdist_kernel<<<grid, 256, SMEM_TOTAL>>>(out);
}